// round 17
// baseline (speedup 1.0000x reference)
#include <cuda_runtime.h>
#include <cuda_bf16.h>
#include <cstdint>

#define NN 10000
#define EE 40000
#define GG 128
#define NF 92
#define EF 50
#define HH 64
#define NHD 10
#define GD 108
#define LL 5
#define FPH 640   // NH*H

#define HN_BLKS 79          // ceil(10000/128)
#define P_BLKS 313          // ceil(40000/128)

// ---------------- device scratch (static, no runtime alloc) ----------------
__device__ float g_h[NN * HH];
__device__ float g_init[NN * HH];
__device__ float g_ea[EE * HH];
__device__ float g_Hn[NN * FPH];              // h @ W[:64]  (25.6 MB, L2-resident)
__device__ __nv_bfloat16 g_Pb[EE * FPH];      // ea @ W[64:] (51.2 MB, bf16)
__device__ float g_agg[NN * HH];
__device__ float g_score[NN];
__device__ float g_smax[GG];
__device__ float g_den[GG];
__device__ float g_pool[GG * HH];

__device__ __forceinline__ float lrelu(float v) { return v > 0.f ? v : 0.2f * v; }

__device__ __forceinline__ float warp_sum(float v) {
    v += __shfl_down_sync(0xffffffffu, v, 16);
    v += __shfl_down_sync(0xffffffffu, v, 8);
    v += __shfl_down_sync(0xffffffffu, v, 4);
    v += __shfl_down_sync(0xffffffffu, v, 2);
    v += __shfl_down_sync(0xffffffffu, v, 1);
    return v;
}

__device__ __forceinline__ void atomicMaxFloat(float* addr, float val) {
    int* ai = (int*)addr;
    int old = *ai;
    while (__int_as_float(old) < val) {
        int assumed = old;
        old = atomicCAS(ai, assumed, __float_as_int(val));
        if (old == assumed) break;
    }
}

__device__ __forceinline__ uint32_t tf32_of(float f) {
    uint32_t r;
    asm("cvt.rna.tf32.f32 %0, %1;" : "=r"(r) : "f"(f));
    return r;
}

// k-position permute: logical k (0..63) -> storage pos so (k, k+4) are adjacent
__device__ __forceinline__ int kpos(int k) {
    return (k >> 3) * 8 + 2 * (k & 3) + ((k >> 2) & 1);
}

// ---------------- embeddings ----------------
__global__ void embed_node_kernel(const float* __restrict__ x,
                                  const float* __restrict__ W,
                                  const float* __restrict__ b) {
    int n = blockIdx.x;
    int t = threadIdx.x;
    __shared__ float xs[NF];
    for (int k = t; k < NF; k += 64) xs[k] = x[n * NF + k];
    __syncthreads();
    float acc = b[t];
    #pragma unroll 4
    for (int k = 0; k < NF; k++) acc = fmaf(xs[k], W[k * HH + t], acc);
    float v = lrelu(acc);
    g_h[n * HH + t] = v;
    g_init[n * HH + t] = v;
}

__global__ void embed_edge_kernel(const float* __restrict__ ea,
                                  const float* __restrict__ W,
                                  const float* __restrict__ b) {
    int e = blockIdx.x;
    int t = threadIdx.x;
    __shared__ float xs[EF];
    if (t < EF) xs[t] = ea[e * EF + t];
    __syncthreads();
    float acc = b[t];
    #pragma unroll 5
    for (int k = 0; k < EF; k++) acc = fmaf(xs[k], W[k * HH + t], acc);
    g_ea[e * HH + t] = lrelu(acc);
}

__global__ void init_misc_kernel() {
    int idx = blockIdx.x * 256 + threadIdx.x;
    if (idx < NN * HH) g_agg[idx] = 0.f;
    if (idx < GG * HH) g_pool[idx] = 0.f;
    if (idx < GG) { g_smax[idx] = -3.0e38f; g_den[idx] = 0.f; }
}

// ---------------- layer GEMM (tf32 tensor cores, staged epilogue) -----------
// C[M,640] = A[M,64] @ W[64,640], 128x128 tile, 8 warps (2m x 4n), warp 64x32.
struct GemmSM {
    float As[128 * 72];   // [m][kpos], pitch 72
    float Bs[128 * 72];   // [n][kpos ^ swz], pitch 72
};
// epilogue stage reuses the same memory: float stage[128][132] (67.6KB < 73.7KB)

__global__ void __launch_bounds__(256, 2)
gemm_layer_kernel(const float* __restrict__ Wbase) {
    extern __shared__ char smraw[];
    GemmSM* s = (GemmSM*)smraw;

    const float* A;
    const float* W;
    int M, bm;
    bool is_hn;
    if (blockIdx.x < HN_BLKS) {
        A = g_h;  W = Wbase;                    M = NN; is_hn = true;
        bm = blockIdx.x * 128;
    } else {
        A = g_ea; W = Wbase + (size_t)HH * FPH; M = EE; is_hn = false;
        bm = (blockIdx.x - HN_BLKS) * 128;
    }
    int bn = blockIdx.y * 128;
    int tid = threadIdx.x;

    // ---- load A tile [128 x 64] -> As[m][kpos] (tf32) ----
    #pragma unroll
    for (int li = 0; li < 8; li++) {
        int i = tid + li * 256;
        int r = i >> 4;
        int kc = (i & 15) * 4;
        int m = bm + r;
        float4 v = make_float4(0.f, 0.f, 0.f, 0.f);
        if (m < M) v = *(const float4*)&A[(size_t)m * 64 + kc];
        float vv[4] = {v.x, v.y, v.z, v.w};
        #pragma unroll
        for (int q = 0; q < 4; q++)
            s->As[r * 72 + kpos(kc + q)] = __uint_as_float(tf32_of(vv[q]));
    }
    // ---- load B tile W[64][128] -> Bs[n][kpos^swz] (tf32) ----
    #pragma unroll
    for (int li = 0; li < 8; li++) {
        int i = tid + li * 256;
        int r = i >> 5;
        int c = (i & 31) * 4;
        float4 v = *(const float4*)&W[(size_t)r * FPH + bn + c];
        float vv[4] = {v.x, v.y, v.z, v.w};
        int kp = kpos(r);
        #pragma unroll
        for (int q = 0; q < 4; q++) {
            int n = c + q;
            int colp = kp ^ (((n >> 2) & 7) << 3);
            s->Bs[n * 72 + colp] = __uint_as_float(tf32_of(vv[q]));
        }
    }
    __syncthreads();

    int lane = tid & 31;
    int warp = tid >> 5;
    int warp_m = warp >> 2;
    int warp_n = warp & 3;
    int g = lane >> 2;
    int t = lane & 3;

    float acc[4][4][4];
    #pragma unroll
    for (int mt = 0; mt < 4; mt++)
        #pragma unroll
        for (int nt = 0; nt < 4; nt++)
            #pragma unroll
            for (int q = 0; q < 4; q++) acc[mt][nt][q] = 0.f;

    #pragma unroll
    for (int ks = 0; ks < 8; ks++) {
        uint32_t a[4][4];
        #pragma unroll
        for (int mt = 0; mt < 4; mt++) {
            int row = warp_m * 64 + mt * 16 + g;
            float2 p02 = *(const float2*)&s->As[row * 72 + ks * 8 + 2 * t];
            float2 p13 = *(const float2*)&s->As[(row + 8) * 72 + ks * 8 + 2 * t];
            a[mt][0] = __float_as_uint(p02.x);
            a[mt][2] = __float_as_uint(p02.y);
            a[mt][1] = __float_as_uint(p13.x);
            a[mt][3] = __float_as_uint(p13.y);
        }
        uint32_t b[4][2];
        #pragma unroll
        for (int nt = 0; nt < 4; nt++) {
            int n = warp_n * 32 + nt * 8 + g;
            int colp = (ks * 8 + 2 * t) ^ (((n >> 2) & 7) << 3);
            float2 q01 = *(const float2*)&s->Bs[n * 72 + colp];
            b[nt][0] = __float_as_uint(q01.x);
            b[nt][1] = __float_as_uint(q01.y);
        }
        #pragma unroll
        for (int mt = 0; mt < 4; mt++)
            #pragma unroll
            for (int nt = 0; nt < 4; nt++) {
                asm volatile(
                    "mma.sync.aligned.m16n8k8.row.col.f32.tf32.tf32.f32 "
                    "{%0,%1,%2,%3}, {%4,%5,%6,%7}, {%8,%9}, {%0,%1,%2,%3};"
                    : "+f"(acc[mt][nt][0]), "+f"(acc[mt][nt][1]),
                      "+f"(acc[mt][nt][2]), "+f"(acc[mt][nt][3])
                    : "r"(a[mt][0]), "r"(a[mt][1]), "r"(a[mt][2]), "r"(a[mt][3]),
                      "r"(b[nt][0]), "r"(b[nt][1]));
            }
    }

    // ---- staged epilogue: acc -> smem -> coalesced global stores ----
    __syncthreads();
    float* stage = (float*)smraw;   // [128][132]
    #pragma unroll
    for (int mt = 0; mt < 4; mt++) {
        int r0 = warp_m * 64 + mt * 16 + g;
        int r1 = r0 + 8;
        #pragma unroll
        for (int nt = 0; nt < 4; nt++) {
            int c = warp_n * 32 + nt * 8 + 2 * t;
            *(float2*)&stage[r0 * 132 + c] = make_float2(acc[mt][nt][0], acc[mt][nt][1]);
            *(float2*)&stage[r1 * 132 + c] = make_float2(acc[mt][nt][2], acc[mt][nt][3]);
        }
    }
    __syncthreads();

    if (is_hn) {
        #pragma unroll
        for (int l = 0; l < 16; l++) {
            int i = tid + l * 256;       // float4 id, 4096 total
            int r = i >> 5;
            int c = (i & 31) * 4;
            int m = bm + r;
            if (m < M) {
                float4 v = *(const float4*)&stage[r * 132 + c];
                *(float4*)&g_Hn[(size_t)m * FPH + bn + c] = v;
            }
        }
    } else {
        #pragma unroll
        for (int l = 0; l < 8; l++) {
            int i = tid + l * 256;       // 8-float chunk id, 2048 total
            int r = i >> 4;
            int c = (i & 15) * 8;
            int m = bm + r;
            if (m < M) {
                float4 v0 = *(const float4*)&stage[r * 132 + c];
                float4 v1 = *(const float4*)&stage[r * 132 + c + 4];
                __nv_bfloat162 o[4];
                o[0] = __floats2bfloat162_rn(v0.x, v0.y);
                o[1] = __floats2bfloat162_rn(v0.z, v0.w);
                o[2] = __floats2bfloat162_rn(v1.x, v1.y);
                o[3] = __floats2bfloat162_rn(v1.z, v1.w);
                *(uint4*)&g_Pb[(size_t)m * FPH + bn + c] = *(uint4*)o;
            }
        }
    }
}

// ---------------- edge kernel: warp-per-edge, bf16 P -------------------------
__global__ void __launch_bounds__(256)
edge_kernel(const float* __restrict__ att,
            const float* __restrict__ gamma,
            const float* __restrict__ beta,
            const int* __restrict__ ei) {
    const float inv_std = 0.99999500003749969f; // 1/sqrt(1+1e-5)
    int lane = threadIdx.x & 31;
    int warp = threadIdx.x >> 5;
    int e = blockIdx.x * 8 + warp;

    int row = ei[e];
    int col = ei[EE + e];
    int half = lane >> 4;
    int c4 = (lane & 15) * 4;

    const __nv_bfloat16* Pp = g_Pb + (size_t)e * FPH;
    const float* Hr = g_Hn + (size_t)row * FPH;
    const float* Hc = g_Hn + (size_t)col * FPH;

    float hj[5][4];
    float ap[5];
    #pragma unroll
    for (int p = 0; p < 5; p++) {
        int off = p * 128 + lane * 4;
        uint2 praw = *(const uint2*)(Pp + off);
        float2 p01 = __bfloat1622float2(*(__nv_bfloat162*)&praw.x);
        float2 p23 = __bfloat1622float2(*(__nv_bfloat162*)&praw.y);
        float4 hr = *(const float4*)(Hr + off);
        float4 hc = *(const float4*)(Hc + off);
        int hd = 2 * p + half;
        float4 a1 = *(const float4*)(att + hd * 128 + c4);
        float4 a2 = *(const float4*)(att + hd * 128 + 64 + c4);
        float pr[4]  = {p01.x, p01.y, p23.x, p23.y};
        float hrr[4] = {hr.x, hr.y, hr.z, hr.w};
        float hcr[4] = {hc.x, hc.y, hc.z, hc.w};
        float a1r[4] = {a1.x, a1.y, a1.z, a1.w};
        float a2r[4] = {a2.x, a2.y, a2.z, a2.w};
        float sacc = 0.f;
        #pragma unroll
        for (int q = 0; q < 4; q++) {
            float hi  = lrelu(hrr[q] + pr[q]);
            float hjq = lrelu(hcr[q] + pr[q]);
            hj[p][q] = hjq;
            sacc = fmaf(hi, a1r[q], sacc);
            sacc = fmaf(hjq, a2r[q], sacc);
        }
        ap[p] = sacc;
    }
    #pragma unroll
    for (int p = 0; p < 5; p++) {
        #pragma unroll
        for (int off = 8; off > 0; off >>= 1)
            ap[p] += __shfl_xor_sync(0xffffffffu, ap[p], off, 16);
    }
    float v[5];
    float mx = -3.0e38f;
    #pragma unroll
    for (int p = 0; p < 5; p++) {
        int hd = 2 * p + half;
        float t = lrelu(ap[p]);
        t = fmaf(t * inv_std, gamma[hd], beta[hd]);
        v[p] = t;
        mx = fmaxf(mx, t);
    }
    mx = fmaxf(mx, __shfl_xor_sync(0xffffffffu, mx, 16));
    float ssum = 0.f;
    #pragma unroll
    for (int p = 0; p < 5; p++) { v[p] = __expf(v[p] - mx); ssum += v[p]; }
    ssum += __shfl_xor_sync(0xffffffffu, ssum, 16);
    float sc = 0.1f / ssum;
    float m[4] = {0.f, 0.f, 0.f, 0.f};
    #pragma unroll
    for (int p = 0; p < 5; p++) {
        float al = v[p] * sc;
        #pragma unroll
        for (int q = 0; q < 4; q++) m[q] = fmaf(al, hj[p][q], m[q]);
    }
    #pragma unroll
    for (int q = 0; q < 4; q++) m[q] += __shfl_xor_sync(0xffffffffu, m[q], 16);
    float* dst = g_agg + row * HH + c4;
    if (half == 0) { atomicAdd(dst + 0, m[0]); atomicAdd(dst + 1, m[1]); }
    else           { atomicAdd(dst + 2, m[2]); atomicAdd(dst + 3, m[3]); }
}

// ---------------- node update ----------------
__global__ void node_update_kernel(const float* __restrict__ b, int flags) {
    int idx = blockIdx.x * 256 + threadIdx.x;
    if (idx >= NN * HH) return;
    int t = idx & 63;
    float v = g_agg[idx] + b[t];
    if (flags & 1) v += g_h[idx];
    if (flags & 2) v += g_init[idx];
    g_h[idx] = v;
    g_agg[idx] = 0.f;
}

// ---------------- readout ----------------
__global__ void score_kernel(const int* __restrict__ batch,
                             const float* __restrict__ gfeat,
                             const float* __restrict__ W1,
                             const float* __restrict__ b1,
                             const float* __restrict__ W2,
                             const float* __restrict__ b2) {
    int n = blockIdx.x;
    int t = threadIdx.x;
    __shared__ float cat_s[HH + GD];
    __shared__ float wr[2];
    int bidx = batch[n];
    cat_s[t] = g_h[n * HH + t];
    for (int k = t; k < GD; k += 64) cat_s[HH + k] = gfeat[bidx * GD + k];
    __syncthreads();
    float acc = b1[t];
    #pragma unroll 4
    for (int k = 0; k < HH + GD; k++) acc = fmaf(cat_s[k], W1[k * HH + t], acc);
    float sv = lrelu(acc);
    float v = warp_sum(sv * W2[t]);
    if ((t & 31) == 0) wr[t >> 5] = v;
    __syncthreads();
    if (t == 0) g_score[n] = wr[0] + wr[1] + b2[0];
}

__global__ void smax_kernel(const int* __restrict__ batch) {
    int n = blockIdx.x * 256 + threadIdx.x;
    if (n >= NN) return;
    atomicMaxFloat(&g_smax[batch[n]], g_score[n]);
}

__global__ void expden_kernel(const int* __restrict__ batch) {
    int n = blockIdx.x * 256 + threadIdx.x;
    if (n >= NN) return;
    int b = batch[n];
    float ex = __expf(g_score[n] - g_smax[b]);
    g_score[n] = ex;
    atomicAdd(&g_den[b], ex);
}

__global__ void pool_kernel(const int* __restrict__ batch) {
    int n = blockIdx.x;
    int t = threadIdx.x;
    int b = batch[n];
    float w = g_score[n] / g_den[b];
    atomicAdd(&g_pool[b * HH + t], g_h[n * HH + t] * w);
}

__global__ void out_kernel(const float* __restrict__ W1,
                           const float* __restrict__ b1,
                           const float* __restrict__ W2,
                           const float* __restrict__ b2,
                           float* __restrict__ out) {
    int g = blockIdx.x;
    int t = threadIdx.x;
    __shared__ float ps[HH];
    __shared__ float wr[2];
    ps[t] = g_pool[g * HH + t];
    __syncthreads();
    float acc = b1[t];
    #pragma unroll 4
    for (int k = 0; k < HH; k++) acc = fmaf(ps[k], W1[k * HH + t], acc);
    float r = fmaxf(acc, 0.f);
    float v = warp_sum(r * W2[t]);
    if ((t & 31) == 0) wr[t >> 5] = v;
    __syncthreads();
    if (t == 0) out[g] = wr[0] + wr[1] + b2[0];
}

// ---------------- launch ----------------
extern "C" void kernel_launch(void* const* d_in, const int* in_sizes, int n_in,
                              void* d_out, int out_size) {
    const float* x        = (const float*)d_in[0];
    const int*   ei       = (const int*)  d_in[1];
    const float* eattr    = (const float*)d_in[2];
    const int*   batch    = (const int*)  d_in[3];
    const float* gfeat    = (const float*)d_in[4];
    const float* node_W   = (const float*)d_in[5];
    const float* node_b   = (const float*)d_in[6];
    const float* edge_W   = (const float*)d_in[7];
    const float* edge_b   = (const float*)d_in[8];
    const float* conv_W   = (const float*)d_in[9];
    const float* conv_att = (const float*)d_in[10];
    const float* conv_b   = (const float*)d_in[11];
    const float* conv_g   = (const float*)d_in[12];
    const float* conv_be  = (const float*)d_in[13];
    const float* ga_W1    = (const float*)d_in[14];
    const float* ga_b1    = (const float*)d_in[15];
    const float* ga_W2    = (const float*)d_in[16];
    const float* ga_b2    = (const float*)d_in[17];
    const float* out_W1   = (const float*)d_in[18];
    const float* out_b1   = (const float*)d_in[19];
    const float* out_W2   = (const float*)d_in[20];
    const float* out_b2   = (const float*)d_in[21];
    float* out = (float*)d_out;

    cudaFuncSetAttribute(gemm_layer_kernel,
                         cudaFuncAttributeMaxDynamicSharedMemorySize,
                         (int)sizeof(GemmSM));

    embed_node_kernel<<<NN, 64>>>(x, node_W, node_b);
    embed_edge_kernel<<<EE, 64>>>(eattr, edge_W, edge_b);
    init_misc_kernel<<<(NN * HH + 255) / 256, 256>>>();

    for (int i = 0; i < LL; i++) {
        const float* Wi = conv_W + (size_t)i * 2 * HH * FPH;
        gemm_layer_kernel<<<dim3(HN_BLKS + P_BLKS, FPH / 128), 256,
                            sizeof(GemmSM)>>>(Wi);
        edge_kernel<<<EE / 8, 256>>>(conv_att + (size_t)i * NHD * 2 * HH,
                                     conv_g + i * NHD, conv_be + i * NHD, ei);
        int flags = (i > 0 ? 1 : 0) | (i == LL - 1 ? 2 : 0);
        node_update_kernel<<<(NN * HH + 255) / 256, 256>>>(conv_b + i * HH, flags);
    }

    score_kernel<<<NN, 64>>>(batch, gfeat, ga_W1, ga_b1, ga_W2, ga_b2);
    smax_kernel<<<(NN + 255) / 256, 256>>>(batch);
    expden_kernel<<<(NN + 255) / 256, 256>>>(batch);
    pool_kernel<<<NN, 64>>>(batch);
    out_kernel<<<GG, 64>>>(out_W1, out_b1, out_W2, out_b2, out);
}